// round 5
// baseline (speedup 1.0000x reference)
#include <cuda_runtime.h>

// Mean-shift clustering, 3 iterations.
//   S = X^T X            [N,N], k = 256
//   K = exp(6 * S)
//   colsum[m] = sum_n K[n,m]
//   Out = (X @ K) / colsum      (eta = 1.0 -> the (1-eta)*X term vanishes)
// Out of iteration t feeds iteration t+1; the 3 outputs land in consecutive
// [256, 8192] slices of d_out.
//
// Per iteration: two fp32 SGEMM-style kernels.
//   Kernel A: 128x128 tile of K = exp(6 * X^T X) -> __device__ scratch.
//   Kernel B: 128x128 tile of Out = (X @ K) * (1/colsum); colsum computed on
//             the fly from the K tiles each block already streams (no atomics).
// Both kernels double-buffer global loads in registers: chunk i+1 loads are
// issued before chunk i compute, hiding L2/DRAM latency under FFMA.

#define NPTS  8192
#define DFEAT 256
#define DELTA 6.0f
#define KT    16
#define BT    128

// 256 MB scratch for the materialized affinity matrix K. __device__ globals
// are the sanctioned scratch mechanism (no runtime allocation anywhere).
__device__ float g_K[(size_t)NPTS * (size_t)NPTS];

// ---------------------------------------------------------------------------
// Kernel A: K[n,m] = exp(DELTA * sum_d X[d,n] * X[d,m])
// Block tile 128(n) x 128(m); k = DFEAT = 256 in chunks of 16.
// 256 threads, 8x8 accumulator per thread.
// ---------------------------------------------------------------------------
__global__ __launch_bounds__(256, 2)
void ms_gemm1_exp(const float* __restrict__ X) {
    const int n0 = blockIdx.y * BT;
    const int m0 = blockIdx.x * BT;

    __shared__ float As[KT][BT];   // X[k, n0 + *]
    __shared__ float Bs[KT][BT];   // X[k, m0 + *]

    const int tid = threadIdx.x;
    const int tx = tid & 15;       // m sub-tile
    const int ty = tid >> 4;       // n sub-tile
    const int lr = tid >> 4;       // load row within k-chunk
    const int lc = (tid & 15) * 8; // load col (8 floats / thread)

    float acc[8][8];
#pragma unroll
    for (int i = 0; i < 8; ++i)
#pragma unroll
        for (int j = 0; j < 8; ++j) acc[i][j] = 0.0f;

    // Preload chunk 0.
    float4 a0 = *reinterpret_cast<const float4*>(X + (size_t)lr * NPTS + n0 + lc);
    float4 a1 = *reinterpret_cast<const float4*>(X + (size_t)lr * NPTS + n0 + lc + 4);
    float4 b0 = *reinterpret_cast<const float4*>(X + (size_t)lr * NPTS + m0 + lc);
    float4 b1 = *reinterpret_cast<const float4*>(X + (size_t)lr * NPTS + m0 + lc + 4);

    for (int kk = 0; kk < DFEAT; kk += KT) {
        __syncthreads();  // previous chunk fully consumed
        *reinterpret_cast<float4*>(&As[lr][lc])     = a0;
        *reinterpret_cast<float4*>(&As[lr][lc + 4]) = a1;
        *reinterpret_cast<float4*>(&Bs[lr][lc])     = b0;
        *reinterpret_cast<float4*>(&Bs[lr][lc + 4]) = b1;
        __syncthreads();

        // Issue next chunk's loads BEFORE compute so latency overlaps FFMA.
        if (kk + KT < DFEAT) {
            const size_t r = (size_t)(kk + KT + lr) * NPTS;
            a0 = *reinterpret_cast<const float4*>(X + r + n0 + lc);
            a1 = *reinterpret_cast<const float4*>(X + r + n0 + lc + 4);
            b0 = *reinterpret_cast<const float4*>(X + r + m0 + lc);
            b1 = *reinterpret_cast<const float4*>(X + r + m0 + lc + 4);
        }

#pragma unroll
        for (int k = 0; k < KT; ++k) {
            const float4 av0 = *reinterpret_cast<const float4*>(&As[k][ty * 8]);
            const float4 av1 = *reinterpret_cast<const float4*>(&As[k][ty * 8 + 4]);
            const float4 bv0 = *reinterpret_cast<const float4*>(&Bs[k][tx * 8]);
            const float4 bv1 = *reinterpret_cast<const float4*>(&Bs[k][tx * 8 + 4]);
            const float a[8] = {av0.x, av0.y, av0.z, av0.w, av1.x, av1.y, av1.z, av1.w};
            const float b[8] = {bv0.x, bv0.y, bv0.z, bv0.w, bv1.x, bv1.y, bv1.z, bv1.w};
#pragma unroll
            for (int i = 0; i < 8; ++i)
#pragma unroll
                for (int j = 0; j < 8; ++j) acc[i][j] += a[i] * b[j];
        }
    }

    // Epilogue: exponentiate, store K tile (coalesced float4 pairs).
#pragma unroll
    for (int i = 0; i < 8; ++i) {
        float4 v0, v1;
        v0.x = __expf(DELTA * acc[i][0]);
        v0.y = __expf(DELTA * acc[i][1]);
        v0.z = __expf(DELTA * acc[i][2]);
        v0.w = __expf(DELTA * acc[i][3]);
        v1.x = __expf(DELTA * acc[i][4]);
        v1.y = __expf(DELTA * acc[i][5]);
        v1.z = __expf(DELTA * acc[i][6]);
        v1.w = __expf(DELTA * acc[i][7]);
        float* p = g_K + (size_t)(n0 + ty * 8 + i) * NPTS + m0 + tx * 8;
        *reinterpret_cast<float4*>(p)     = v0;
        *reinterpret_cast<float4*>(p + 4) = v1;
    }
}

// ---------------------------------------------------------------------------
// Kernel B: Out[d,m] = (sum_n X[d,n] * K[n,m]) / (sum_n K[n,m])
// Block tile 128(d) x 128(m); grid.y = 2 covers d = 0..255.
// colsum accumulated from the K tiles this block streams anyway (each d-block
// recomputes it redundantly -- cheaper than atomics + an init pass).
// ---------------------------------------------------------------------------
__global__ __launch_bounds__(256, 2)
void ms_gemm2_scale(const float* __restrict__ X, float* __restrict__ Out) {
    const int m0 = blockIdx.x * BT;
    const int d0 = blockIdx.y * BT;

    __shared__ float As[KT][BT + 4];   // transposed X tile: As[k][d]
    __shared__ float Bs[KT][BT];       // K[n-chunk, m-tile]
    __shared__ float Cs[KT][BT];       // colsum partials
    __shared__ float inv_colsum[BT];

    const int tid = threadIdx.x;
    const int tx = tid & 15;
    const int ty = tid >> 4;
    const int lr = tid >> 4;
    const int lc = (tid & 15) * 8;
    const int ad = tid >> 1;          // d row for A-tile load
    const int ak = (tid & 1) * 8;     // k offset for A-tile load

    float acc[8][8];
#pragma unroll
    for (int i = 0; i < 8; ++i)
#pragma unroll
        for (int j = 0; j < 8; ++j) acc[i][j] = 0.0f;
    float cs[8] = {0.f, 0.f, 0.f, 0.f, 0.f, 0.f, 0.f, 0.f};

    // Preload chunk 0.
    float4 a0 = *reinterpret_cast<const float4*>(X + (size_t)(d0 + ad) * NPTS + ak);
    float4 a1 = *reinterpret_cast<const float4*>(X + (size_t)(d0 + ad) * NPTS + ak + 4);
    float4 b0 = *reinterpret_cast<const float4*>(g_K + (size_t)lr * NPTS + m0 + lc);
    float4 b1 = *reinterpret_cast<const float4*>(g_K + (size_t)lr * NPTS + m0 + lc + 4);

    for (int nk = 0; nk < NPTS; nk += KT) {
        __syncthreads();
        // Transposed store so the compute loop reads A k-major.
        As[ak + 0][ad] = a0.x; As[ak + 1][ad] = a0.y;
        As[ak + 2][ad] = a0.z; As[ak + 3][ad] = a0.w;
        As[ak + 4][ad] = a1.x; As[ak + 5][ad] = a1.y;
        As[ak + 6][ad] = a1.z; As[ak + 7][ad] = a1.w;
        *reinterpret_cast<float4*>(&Bs[lr][lc])     = b0;
        *reinterpret_cast<float4*>(&Bs[lr][lc + 4]) = b1;
        // colsum partials: this thread owns rows {lr + 16t} of cols lc..lc+7.
        cs[0] += b0.x; cs[1] += b0.y; cs[2] += b0.z; cs[3] += b0.w;
        cs[4] += b1.x; cs[5] += b1.y; cs[6] += b1.z; cs[7] += b1.w;
        __syncthreads();

        if (nk + KT < NPTS) {
            a0 = *reinterpret_cast<const float4*>(X + (size_t)(d0 + ad) * NPTS + nk + KT + ak);
            a1 = *reinterpret_cast<const float4*>(X + (size_t)(d0 + ad) * NPTS + nk + KT + ak + 4);
            b0 = *reinterpret_cast<const float4*>(g_K + (size_t)(nk + KT + lr) * NPTS + m0 + lc);
            b1 = *reinterpret_cast<const float4*>(g_K + (size_t)(nk + KT + lr) * NPTS + m0 + lc + 4);
        }

#pragma unroll
        for (int k = 0; k < KT; ++k) {
            const float4 av0 = *reinterpret_cast<const float4*>(&As[k][ty * 8]);
            const float4 av1 = *reinterpret_cast<const float4*>(&As[k][ty * 8 + 4]);
            const float4 bv0 = *reinterpret_cast<const float4*>(&Bs[k][tx * 8]);
            const float4 bv1 = *reinterpret_cast<const float4*>(&Bs[k][tx * 8 + 4]);
            const float a[8] = {av0.x, av0.y, av0.z, av0.w, av1.x, av1.y, av1.z, av1.w};
            const float b[8] = {bv0.x, bv0.y, bv0.z, bv0.w, bv1.x, bv1.y, bv1.z, bv1.w};
#pragma unroll
            for (int i = 0; i < 8; ++i)
#pragma unroll
                for (int j = 0; j < 8; ++j) acc[i][j] += a[i] * b[j];
        }
    }

    // Reduce colsum partials across the 16 k-rows.
    __syncthreads();
#pragma unroll
    for (int j = 0; j < 8; ++j) Cs[lr][lc + j] = cs[j];
    __syncthreads();
    if (tid < BT) {
        float s = 0.0f;
#pragma unroll
        for (int r = 0; r < KT; ++r) s += Cs[r][tid];
        inv_colsum[tid] = 1.0f / s;
    }
    __syncthreads();

    // Epilogue: scale and store.
#pragma unroll
    for (int i = 0; i < 8; ++i) {
        float4 v0, v1;
        v0.x = acc[i][0] * inv_colsum[tx * 8 + 0];
        v0.y = acc[i][1] * inv_colsum[tx * 8 + 1];
        v0.z = acc[i][2] * inv_colsum[tx * 8 + 2];
        v0.w = acc[i][3] * inv_colsum[tx * 8 + 3];
        v1.x = acc[i][4] * inv_colsum[tx * 8 + 4];
        v1.y = acc[i][5] * inv_colsum[tx * 8 + 5];
        v1.z = acc[i][6] * inv_colsum[tx * 8 + 6];
        v1.w = acc[i][7] * inv_colsum[tx * 8 + 7];
        float* p = Out + (size_t)(d0 + ty * 8 + i) * NPTS + m0 + tx * 8;
        *reinterpret_cast<float4*>(p)     = v0;
        *reinterpret_cast<float4*>(p + 4) = v1;
    }
}

// ---------------------------------------------------------------------------
// Launch: 3 chained iterations; output slice t feeds iteration t+1.
// Kernel launches only on the default stream -> graph-capturable.
// ---------------------------------------------------------------------------
extern "C" void kernel_launch(void* const* d_in, const int* in_sizes, int n_in,
                              void* d_out, int out_size) {
    const float* X0 = (const float*)d_in[0];
    float* out = (float*)d_out;

    const dim3 blk(256);
    const dim3 gA(NPTS / BT, NPTS / BT);   // 64 x 64
    const dim3 gB(NPTS / BT, DFEAT / BT);  // 64 x 2

    const float* cur = X0;
    for (int t = 0; t < 3; ++t) {
        float* O = out + (size_t)t * DFEAT * NPTS;
        ms_gemm1_exp<<<gA, blk>>>(cur);
        ms_gemm2_scale<<<gB, blk>>>(cur, O);
        cur = O;
    }
}

// round 9
// speedup vs baseline: 2.4076x; 2.4076x over previous
#include <cuda_runtime.h>
#include <cstdint>

// Mean-shift clustering, 3 iterations, tf32 mma.sync tensor-core version.
// (tcgen05 is unavailable: the harness builds through compute_103 (non-'a'),
// so only base-PTX features are usable. mma.sync tf32 is sm_80 base PTX.)
//
//   S = X^T X ; K = exp(6 S) (symmetric) ; colsum[m] = row-sum of K
//   Out[d,m] = (sum_n K[m,n] X[d,n]) / colsum[m]
//
// GEMM1: D[n,m] 128x128 tile of S via mma.m16n8k8 tf32; epilogue applies exp
//        and writes K transposed (valid by symmetry, coalesced-ish).
// GEMM2: D[m,d] 128x128 tile; A = K row panel, B = X (both k-contiguous).
//        colsum accumulated from raw fp32 values in the prefetch registers.
// All mma operands rounded to tf32 with cvt.rna (zero-mean error).

#define NPTS  8192
#define DFEAT 256
#define DELTA 6.0f
#define KC    16     // k per smem chunk
#define AST   20     // padded smem row stride (floats): conflict-free frags

__device__ float g_K [(size_t)NPTS * NPTS];   // 256 MB affinity scratch
__device__ float g_XT[(size_t)NPTS * DFEAT];  // 8 MB X^T scratch

__device__ __forceinline__ uint32_t f2tf32(float x) {
    uint32_t u;
    asm("cvt.rna.tf32.f32 %0, %1;" : "=r"(u) : "f"(x));
    return u;
}

__device__ __forceinline__ void mma8(float* c, const uint32_t* a, const uint32_t* b) {
    asm volatile(
        "mma.sync.aligned.m16n8k8.row.col.f32.tf32.tf32.f32 "
        "{%0,%1,%2,%3}, {%4,%5,%6,%7}, {%8,%9}, {%0,%1,%2,%3};"
        : "+f"(c[0]), "+f"(c[1]), "+f"(c[2]), "+f"(c[3])
        : "r"(a[0]), "r"(a[1]), "r"(a[2]), "r"(a[3]), "r"(b[0]), "r"(b[1]));
}

// ---------------------------------------------------------------------------
// Transpose: g_XT[n][d] = X[d][n]
// ---------------------------------------------------------------------------
__global__ void __launch_bounds__(256) ms_transpose(const float* __restrict__ X) {
    __shared__ float t[32][33];
    const int tx = threadIdx.x, ty = threadIdx.y;
    const int n0 = blockIdx.x * 32, d0 = blockIdx.y * 32;
#pragma unroll
    for (int i = 0; i < 32; i += 8)
        t[ty + i][tx] = X[(size_t)(d0 + ty + i) * NPTS + n0 + tx];
    __syncthreads();
#pragma unroll
    for (int i = 0; i < 32; i += 8)
        g_XT[(size_t)(n0 + ty + i) * DFEAT + d0 + tx] = t[tx][ty + i];
}

// ---------------------------------------------------------------------------
// GEMM1: g_K = exp(DELTA * X^T X), written transposed (K symmetric).
// Block 128(n) x 128(m), k = 256. 8 warps: warp grid 2(m-rows) x 4(n-cols),
// warp tile 64x32, mma tiles 4x4 of m16n8k8.
// ---------------------------------------------------------------------------
__global__ void __launch_bounds__(256, 2) ms_mma_gemm1() {
    __shared__ uint32_t As[128 * AST];   // XT rows n0..n0+127 (tf32 bits)
    __shared__ uint32_t Bs[128 * AST];   // XT rows m0..m0+127

    const int tid  = threadIdx.x;
    const int n0   = blockIdx.y * 128, m0 = blockIdx.x * 128;
    const int warp = tid >> 5, lane = tid & 31;
    const int g    = lane >> 2, t = lane & 3;
    const int wm   = (warp & 1) * 64;     // row offset of warp tile
    const int wn   = (warp >> 1) * 32;    // col offset of warp tile
    const int srow = tid >> 1;            // staging row (0..127)
    const int scol = (tid & 1) * 8;       // staging col base (0 or 8)

    float C[16][4];
#pragma unroll
    for (int i = 0; i < 16; ++i)
#pragma unroll
        for (int j = 0; j < 4; ++j) C[i][j] = 0.0f;

    const float* gA = g_XT + (size_t)(n0 + srow) * DFEAT + scol;
    const float* gB = g_XT + (size_t)(m0 + srow) * DFEAT + scol;

    float4 pa0 = *reinterpret_cast<const float4*>(gA);
    float4 pa1 = *reinterpret_cast<const float4*>(gA + 4);
    float4 pb0 = *reinterpret_cast<const float4*>(gB);
    float4 pb1 = *reinterpret_cast<const float4*>(gB + 4);

#pragma unroll 1
    for (int c = 0; c < DFEAT / KC; ++c) {
        __syncthreads();
        uint32_t* as = As + srow * AST + scol;
        uint32_t* bs = Bs + srow * AST + scol;
        as[0] = f2tf32(pa0.x); as[1] = f2tf32(pa0.y); as[2] = f2tf32(pa0.z); as[3] = f2tf32(pa0.w);
        as[4] = f2tf32(pa1.x); as[5] = f2tf32(pa1.y); as[6] = f2tf32(pa1.z); as[7] = f2tf32(pa1.w);
        bs[0] = f2tf32(pb0.x); bs[1] = f2tf32(pb0.y); bs[2] = f2tf32(pb0.z); bs[3] = f2tf32(pb0.w);
        bs[4] = f2tf32(pb1.x); bs[5] = f2tf32(pb1.y); bs[6] = f2tf32(pb1.z); bs[7] = f2tf32(pb1.w);
        __syncthreads();

        if (c + 1 < DFEAT / KC) {
            const int o = (c + 1) * KC;
            pa0 = *reinterpret_cast<const float4*>(gA + o);
            pa1 = *reinterpret_cast<const float4*>(gA + o + 4);
            pb0 = *reinterpret_cast<const float4*>(gB + o);
            pb1 = *reinterpret_cast<const float4*>(gB + o + 4);
        }

#pragma unroll
        for (int ks = 0; ks < 2; ++ks) {
            uint32_t bf[4][2];
#pragma unroll
            for (int nt = 0; nt < 4; ++nt) {
                const uint32_t* bp = Bs + (wn + nt * 8 + g) * AST + ks * 8 + t;
                bf[nt][0] = bp[0];
                bf[nt][1] = bp[4];
            }
#pragma unroll
            for (int mt = 0; mt < 4; ++mt) {
                const uint32_t* ap = As + (wm + mt * 16 + g) * AST + ks * 8 + t;
                uint32_t af[4];
                af[0] = ap[0];
                af[1] = ap[8 * AST];
                af[2] = ap[4];
                af[3] = ap[8 * AST + 4];
#pragma unroll
                for (int nt = 0; nt < 4; ++nt) mma8(C[mt * 4 + nt], af, bf[nt]);
            }
        }
    }

    // Epilogue: K[m0+j][n0+i] = exp(DELTA * D[i][j])  (transposed write; K sym.)
#pragma unroll
    for (int mt = 0; mt < 4; ++mt) {
#pragma unroll
        for (int nt = 0; nt < 4; ++nt) {
            const float* cc = C[mt * 4 + nt];
            const int i0 = wm + mt * 16 + g;
            const int j0 = wn + nt * 8 + 2 * t;
            float* r0 = g_K + (size_t)(m0 + j0) * NPTS + n0 + i0;
            float* r1 = g_K + (size_t)(m0 + j0 + 1) * NPTS + n0 + i0;
            r0[0] = __expf(DELTA * cc[0]);
            r1[0] = __expf(DELTA * cc[1]);
            r0[8] = __expf(DELTA * cc[2]);
            r1[8] = __expf(DELTA * cc[3]);
        }
    }
}

// ---------------------------------------------------------------------------
// GEMM2: Out[d,m] = (sum_n K[m,n] X[d,n]) / colsum[m]
// Block 128(m) x 128(d), k = 8192; grid.y = 2 covers d = 0..255.
// colsum accumulated from the raw fp32 prefetch registers during A staging.
// ---------------------------------------------------------------------------
__global__ void __launch_bounds__(256, 2) ms_mma_gemm2(const float* __restrict__ Xc,
                                                       float* __restrict__ Out) {
    __shared__ uint32_t As[128 * AST];   // K rows m0..m0+127
    __shared__ uint32_t Bs[128 * AST];   // X rows d0..d0+127
    __shared__ float cs_sm[128];

    const int tid  = threadIdx.x;
    const int m0   = blockIdx.x * 128, d0 = blockIdx.y * 128;
    const int warp = tid >> 5, lane = tid & 31;
    const int g    = lane >> 2, t = lane & 3;
    const int wm   = (warp & 1) * 64;
    const int wn   = (warp >> 1) * 32;
    const int srow = tid >> 1;
    const int scol = (tid & 1) * 8;

    float C[16][4];
#pragma unroll
    for (int i = 0; i < 16; ++i)
#pragma unroll
        for (int j = 0; j < 4; ++j) C[i][j] = 0.0f;
    float csum = 0.0f;

    const float* gA = g_K + (size_t)(m0 + srow) * NPTS + scol;
    const float* gB = Xc  + (size_t)(d0 + srow) * NPTS + scol;

    float4 pa0 = *reinterpret_cast<const float4*>(gA);
    float4 pa1 = *reinterpret_cast<const float4*>(gA + 4);
    float4 pb0 = *reinterpret_cast<const float4*>(gB);
    float4 pb1 = *reinterpret_cast<const float4*>(gB + 4);

#pragma unroll 1
    for (int c = 0; c < NPTS / KC; ++c) {
        __syncthreads();
        uint32_t* as = As + srow * AST + scol;
        uint32_t* bs = Bs + srow * AST + scol;
        as[0] = f2tf32(pa0.x); as[1] = f2tf32(pa0.y); as[2] = f2tf32(pa0.z); as[3] = f2tf32(pa0.w);
        as[4] = f2tf32(pa1.x); as[5] = f2tf32(pa1.y); as[6] = f2tf32(pa1.z); as[7] = f2tf32(pa1.w);
        bs[0] = f2tf32(pb0.x); bs[1] = f2tf32(pb0.y); bs[2] = f2tf32(pb0.z); bs[3] = f2tf32(pb0.w);
        bs[4] = f2tf32(pb1.x); bs[5] = f2tf32(pb1.y); bs[6] = f2tf32(pb1.z); bs[7] = f2tf32(pb1.w);
        // colsum partial for row m0+srow (raw fp32 K values).
        csum += ((pa0.x + pa0.y) + (pa0.z + pa0.w)) + ((pa1.x + pa1.y) + (pa1.z + pa1.w));
        __syncthreads();

        if (c + 1 < NPTS / KC) {
            const int o = (c + 1) * KC;
            pa0 = *reinterpret_cast<const float4*>(gA + o);
            pa1 = *reinterpret_cast<const float4*>(gA + o + 4);
            pb0 = *reinterpret_cast<const float4*>(gB + o);
            pb1 = *reinterpret_cast<const float4*>(gB + o + 4);
        }

#pragma unroll
        for (int ks = 0; ks < 2; ++ks) {
            uint32_t bf[4][2];
#pragma unroll
            for (int nt = 0; nt < 4; ++nt) {
                const uint32_t* bp = Bs + (wn + nt * 8 + g) * AST + ks * 8 + t;
                bf[nt][0] = bp[0];
                bf[nt][1] = bp[4];
            }
#pragma unroll
            for (int mt = 0; mt < 4; ++mt) {
                const uint32_t* ap = As + (wm + mt * 16 + g) * AST + ks * 8 + t;
                uint32_t af[4];
                af[0] = ap[0];
                af[1] = ap[8 * AST];
                af[2] = ap[4];
                af[3] = ap[8 * AST + 4];
#pragma unroll
                for (int nt = 0; nt < 4; ++nt) mma8(C[mt * 4 + nt], af, bf[nt]);
            }
        }
    }

    // Finish colsum: the two threads (tid, tid^1) share row srow.
    csum += __shfl_xor_sync(0xffffffffu, csum, 1);
    if ((tid & 1) == 0) cs_sm[srow] = csum;
    __syncthreads();

    // Epilogue: Out[d0+j][m0+i] = D[i][j] / colsum[m0+i]
#pragma unroll
    for (int mt = 0; mt < 4; ++mt) {
        const int i0 = wm + mt * 16 + g;
        const float inv0 = 1.0f / cs_sm[i0];
        const float inv1 = 1.0f / cs_sm[i0 + 8];
#pragma unroll
        for (int nt = 0; nt < 4; ++nt) {
            const float* cc = C[mt * 4 + nt];
            const int j0 = wn + nt * 8 + 2 * t;
            float* r0 = Out + (size_t)(d0 + j0) * NPTS + m0 + i0;
            float* r1 = Out + (size_t)(d0 + j0 + 1) * NPTS + m0 + i0;
            r0[0] = cc[0] * inv0;
            r1[0] = cc[1] * inv0;
            r0[8] = cc[2] * inv1;
            r1[8] = cc[3] * inv1;
        }
    }
}

// ---------------------------------------------------------------------------
// Launch: 3 chained iterations; kernel launches only -> graph-capturable.
// ---------------------------------------------------------------------------
extern "C" void kernel_launch(void* const* d_in, const int* in_sizes, int n_in,
                              void* d_out, int out_size) {
    const float* X0 = (const float*)d_in[0];
    float* out = (float*)d_out;

    const float* cur = X0;
    for (int it = 0; it < 3; ++it) {
        float* O = out + (size_t)it * DFEAT * NPTS;
        ms_transpose<<<dim3(NPTS / 32, DFEAT / 32), dim3(32, 8)>>>(cur);
        ms_mma_gemm1<<<dim3(NPTS / 128, NPTS / 128), 256>>>();
        ms_mma_gemm2<<<dim3(NPTS / 128, 2), 256>>>(cur, O);
        cur = O;
    }
}

// round 10
// speedup vs baseline: 2.8697x; 1.1919x over previous
#include <cuda_runtime.h>
#include <cstdint>

// Mean-shift clustering, 3 iterations, tf32 mma.sync tensor-core version.
// (tcgen05 unavailable: harness builds via compute_103 (non-'a'); mma.sync
// tf32 is base sm_80 PTX and runs on the tensor pipe.)
//
//   S = X^T X ; K = exp(6 S) (symmetric) ; colsum[m] = row-sum of K
//   Out[d,m] = (sum_n K[m,n] X[d,n]) / colsum[m]
//
// GEMM1 exploits symmetry: only tile pairs with m-tile >= n-tile are
// computed (2080 of 4096 blocks); each off-diagonal block writes its
// exp-tile twice (transposed scatter -> K[m,n] half, contiguous float2 ->
// K[n,m] half). Diagonal blocks write once.
// GEMM2: A = K row panel, B = X (both k-contiguous); colsum accumulated
// free from the raw fp32 prefetch registers during A staging.
// All mma operands rounded to tf32 with cvt.rna (zero-mean error).

#define NPTS  8192
#define DFEAT 256
#define DELTA 6.0f
#define KC    16     // k per smem chunk
#define AST   20     // padded smem row stride (floats): conflict-free frags

__device__ float g_K [(size_t)NPTS * NPTS];   // 256 MB affinity scratch
__device__ float g_XT[(size_t)NPTS * DFEAT];  // 8 MB X^T scratch

__device__ __forceinline__ uint32_t f2tf32(float x) {
    uint32_t u;
    asm("cvt.rna.tf32.f32 %0, %1;" : "=r"(u) : "f"(x));
    return u;
}

__device__ __forceinline__ void mma8(float* c, const uint32_t* a, const uint32_t* b) {
    asm volatile(
        "mma.sync.aligned.m16n8k8.row.col.f32.tf32.tf32.f32 "
        "{%0,%1,%2,%3}, {%4,%5,%6,%7}, {%8,%9}, {%0,%1,%2,%3};"
        : "+f"(c[0]), "+f"(c[1]), "+f"(c[2]), "+f"(c[3])
        : "r"(a[0]), "r"(a[1]), "r"(a[2]), "r"(a[3]), "r"(b[0]), "r"(b[1]));
}

// ---------------------------------------------------------------------------
// Transpose: g_XT[n][d] = X[d][n]
// ---------------------------------------------------------------------------
__global__ void __launch_bounds__(256) ms_transpose(const float* __restrict__ X) {
    __shared__ float t[32][33];
    const int tx = threadIdx.x, ty = threadIdx.y;
    const int n0 = blockIdx.x * 32, d0 = blockIdx.y * 32;
#pragma unroll
    for (int i = 0; i < 32; i += 8)
        t[ty + i][tx] = X[(size_t)(d0 + ty + i) * NPTS + n0 + tx];
    __syncthreads();
#pragma unroll
    for (int i = 0; i < 32; i += 8)
        g_XT[(size_t)(n0 + ty + i) * DFEAT + d0 + tx] = t[tx][ty + i];
}

// ---------------------------------------------------------------------------
// GEMM1: g_K = exp(DELTA * X^T X), symmetric -> upper-tile-pair blocks only.
// Block 128(n) x 128(m), k = 256. 8 warps: warp grid 2(m) x 4(n),
// warp tile 64x32, mma tiles 4x4 of m16n8k8.
// ---------------------------------------------------------------------------
__global__ void __launch_bounds__(256, 2) ms_mma_gemm1() {
    const int bx = blockIdx.x, by = blockIdx.y;
    if (bx < by) return;                 // lower-triangle tile pair: skip
    const bool diag = (bx == by);

    __shared__ uint32_t As[128 * AST];   // XT rows n0..n0+127 (tf32 bits)
    __shared__ uint32_t Bs[128 * AST];   // XT rows m0..m0+127

    const int tid  = threadIdx.x;
    const int n0   = by * 128, m0 = bx * 128;
    const int warp = tid >> 5, lane = tid & 31;
    const int g    = lane >> 2, t = lane & 3;
    const int wm   = (warp & 1) * 64;     // row offset of warp tile
    const int wn   = (warp >> 1) * 32;    // col offset of warp tile
    const int srow = tid >> 1;            // staging row (0..127)
    const int scol = (tid & 1) * 8;       // staging col base (0 or 8)

    float C[16][4];
#pragma unroll
    for (int i = 0; i < 16; ++i)
#pragma unroll
        for (int j = 0; j < 4; ++j) C[i][j] = 0.0f;

    const float* gA = g_XT + (size_t)(n0 + srow) * DFEAT + scol;
    const float* gB = g_XT + (size_t)(m0 + srow) * DFEAT + scol;

    float4 pa0 = *reinterpret_cast<const float4*>(gA);
    float4 pa1 = *reinterpret_cast<const float4*>(gA + 4);
    float4 pb0 = *reinterpret_cast<const float4*>(gB);
    float4 pb1 = *reinterpret_cast<const float4*>(gB + 4);

#pragma unroll 1
    for (int c = 0; c < DFEAT / KC; ++c) {
        __syncthreads();
        uint32_t* as = As + srow * AST + scol;
        uint32_t* bs = Bs + srow * AST + scol;
        as[0] = f2tf32(pa0.x); as[1] = f2tf32(pa0.y); as[2] = f2tf32(pa0.z); as[3] = f2tf32(pa0.w);
        as[4] = f2tf32(pa1.x); as[5] = f2tf32(pa1.y); as[6] = f2tf32(pa1.z); as[7] = f2tf32(pa1.w);
        bs[0] = f2tf32(pb0.x); bs[1] = f2tf32(pb0.y); bs[2] = f2tf32(pb0.z); bs[3] = f2tf32(pb0.w);
        bs[4] = f2tf32(pb1.x); bs[5] = f2tf32(pb1.y); bs[6] = f2tf32(pb1.z); bs[7] = f2tf32(pb1.w);
        __syncthreads();

        if (c + 1 < DFEAT / KC) {
            const int o = (c + 1) * KC;
            pa0 = *reinterpret_cast<const float4*>(gA + o);
            pa1 = *reinterpret_cast<const float4*>(gA + o + 4);
            pb0 = *reinterpret_cast<const float4*>(gB + o);
            pb1 = *reinterpret_cast<const float4*>(gB + o + 4);
        }

#pragma unroll
        for (int ks = 0; ks < 2; ++ks) {
            uint32_t bf[4][2];
#pragma unroll
            for (int nt = 0; nt < 4; ++nt) {
                const uint32_t* bp = Bs + (wn + nt * 8 + g) * AST + ks * 8 + t;
                bf[nt][0] = bp[0];
                bf[nt][1] = bp[4];
            }
#pragma unroll
            for (int mt = 0; mt < 4; ++mt) {
                const uint32_t* ap = As + (wm + mt * 16 + g) * AST + ks * 8 + t;
                uint32_t af[4];
                af[0] = ap[0];
                af[1] = ap[8 * AST];
                af[2] = ap[4];
                af[3] = ap[8 * AST + 4];
#pragma unroll
                for (int nt = 0; nt < 4; ++nt) mma8(C[mt * 4 + nt], af, bf[nt]);
            }
        }
    }

    // Epilogue. D[i][j] = S[n0+i][m0+j].
    //  - transposed scatter: K[m0+j][n0+i]  (covers row>=col half; full tile
    //    when diagonal)
    //  - mirror (off-diag only): K[n0+i][m0+j] as contiguous float2 stores
#pragma unroll
    for (int mt = 0; mt < 4; ++mt) {
#pragma unroll
        for (int nt = 0; nt < 4; ++nt) {
            const float* cc = C[mt * 4 + nt];
            const int i0 = wm + mt * 16 + g;
            const int j0 = wn + nt * 8 + 2 * t;
            const float e0 = __expf(DELTA * cc[0]);
            const float e1 = __expf(DELTA * cc[1]);
            const float e2 = __expf(DELTA * cc[2]);
            const float e3 = __expf(DELTA * cc[3]);

            float* r0 = g_K + (size_t)(m0 + j0) * NPTS + n0 + i0;
            float* r1 = g_K + (size_t)(m0 + j0 + 1) * NPTS + n0 + i0;
            r0[0] = e0;
            r1[0] = e1;
            r0[8] = e2;
            r1[8] = e3;

            if (!diag) {
                float2 lo = { e0, e1 };
                float2 hi = { e2, e3 };
                *reinterpret_cast<float2*>(g_K + (size_t)(n0 + i0) * NPTS + m0 + j0)     = lo;
                *reinterpret_cast<float2*>(g_K + (size_t)(n0 + i0 + 8) * NPTS + m0 + j0) = hi;
            }
        }
    }
}

// ---------------------------------------------------------------------------
// GEMM2: Out[d,m] = (sum_n K[m,n] X[d,n]) / colsum[m]
// Block 128(m) x 128(d), k = 8192; grid.y = 2 covers d = 0..255.
// colsum accumulated from the raw fp32 prefetch registers during A staging.
// ---------------------------------------------------------------------------
__global__ void __launch_bounds__(256, 2) ms_mma_gemm2(const float* __restrict__ Xc,
                                                       float* __restrict__ Out) {
    __shared__ uint32_t As[128 * AST];   // K rows m0..m0+127
    __shared__ uint32_t Bs[128 * AST];   // X rows d0..d0+127
    __shared__ float cs_sm[128];

    const int tid  = threadIdx.x;
    const int m0   = blockIdx.x * 128, d0 = blockIdx.y * 128;
    const int warp = tid >> 5, lane = tid & 31;
    const int g    = lane >> 2, t = lane & 3;
    const int wm   = (warp & 1) * 64;
    const int wn   = (warp >> 1) * 32;
    const int srow = tid >> 1;
    const int scol = (tid & 1) * 8;

    float C[16][4];
#pragma unroll
    for (int i = 0; i < 16; ++i)
#pragma unroll
        for (int j = 0; j < 4; ++j) C[i][j] = 0.0f;
    float csum = 0.0f;

    const float* gA = g_K + (size_t)(m0 + srow) * NPTS + scol;
    const float* gB = Xc  + (size_t)(d0 + srow) * NPTS + scol;

    float4 pa0 = *reinterpret_cast<const float4*>(gA);
    float4 pa1 = *reinterpret_cast<const float4*>(gA + 4);
    float4 pb0 = *reinterpret_cast<const float4*>(gB);
    float4 pb1 = *reinterpret_cast<const float4*>(gB + 4);

#pragma unroll 1
    for (int c = 0; c < NPTS / KC; ++c) {
        __syncthreads();
        uint32_t* as = As + srow * AST + scol;
        uint32_t* bs = Bs + srow * AST + scol;
        as[0] = f2tf32(pa0.x); as[1] = f2tf32(pa0.y); as[2] = f2tf32(pa0.z); as[3] = f2tf32(pa0.w);
        as[4] = f2tf32(pa1.x); as[5] = f2tf32(pa1.y); as[6] = f2tf32(pa1.z); as[7] = f2tf32(pa1.w);
        bs[0] = f2tf32(pb0.x); bs[1] = f2tf32(pb0.y); bs[2] = f2tf32(pb0.z); bs[3] = f2tf32(pb0.w);
        bs[4] = f2tf32(pb1.x); bs[5] = f2tf32(pb1.y); bs[6] = f2tf32(pb1.z); bs[7] = f2tf32(pb1.w);
        // colsum partial for row m0+srow (raw fp32 K values).
        csum += ((pa0.x + pa0.y) + (pa0.z + pa0.w)) + ((pa1.x + pa1.y) + (pa1.z + pa1.w));
        __syncthreads();

        if (c + 1 < NPTS / KC) {
            const int o = (c + 1) * KC;
            pa0 = *reinterpret_cast<const float4*>(gA + o);
            pa1 = *reinterpret_cast<const float4*>(gA + o + 4);
            pb0 = *reinterpret_cast<const float4*>(gB + o);
            pb1 = *reinterpret_cast<const float4*>(gB + o + 4);
        }

#pragma unroll
        for (int ks = 0; ks < 2; ++ks) {
            uint32_t bf[4][2];
#pragma unroll
            for (int nt = 0; nt < 4; ++nt) {
                const uint32_t* bp = Bs + (wn + nt * 8 + g) * AST + ks * 8 + t;
                bf[nt][0] = bp[0];
                bf[nt][1] = bp[4];
            }
#pragma unroll
            for (int mt = 0; mt < 4; ++mt) {
                const uint32_t* ap = As + (wm + mt * 16 + g) * AST + ks * 8 + t;
                uint32_t af[4];
                af[0] = ap[0];
                af[1] = ap[8 * AST];
                af[2] = ap[4];
                af[3] = ap[8 * AST + 4];
#pragma unroll
                for (int nt = 0; nt < 4; ++nt) mma8(C[mt * 4 + nt], af, bf[nt]);
            }
        }
    }

    // Finish colsum: the two threads (tid, tid^1) share row srow.
    csum += __shfl_xor_sync(0xffffffffu, csum, 1);
    if ((tid & 1) == 0) cs_sm[srow] = csum;
    __syncthreads();

    // Epilogue: Out[d0+j][m0+i] = D[i][j] / colsum[m0+i]
#pragma unroll
    for (int mt = 0; mt < 4; ++mt) {
        const int i0 = wm + mt * 16 + g;
        const float inv0 = 1.0f / cs_sm[i0];
        const float inv1 = 1.0f / cs_sm[i0 + 8];
#pragma unroll
        for (int nt = 0; nt < 4; ++nt) {
            const float* cc = C[mt * 4 + nt];
            const int j0 = wn + nt * 8 + 2 * t;
            float* r0 = Out + (size_t)(d0 + j0) * NPTS + m0 + i0;
            float* r1 = Out + (size_t)(d0 + j0 + 1) * NPTS + m0 + i0;
            r0[0] = cc[0] * inv0;
            r1[0] = cc[1] * inv0;
            r0[8] = cc[2] * inv1;
            r1[8] = cc[3] * inv1;
        }
    }
}

// ---------------------------------------------------------------------------
// Launch: 3 chained iterations; kernel launches only -> graph-capturable.
// ---------------------------------------------------------------------------
extern "C" void kernel_launch(void* const* d_in, const int* in_sizes, int n_in,
                              void* d_out, int out_size) {
    const float* X0 = (const float*)d_in[0];
    float* out = (float*)d_out;

    const float* cur = X0;
    for (int it = 0; it < 3; ++it) {
        float* O = out + (size_t)it * DFEAT * NPTS;
        ms_transpose<<<dim3(NPTS / 32, DFEAT / 32), dim3(32, 8)>>>(cur);
        ms_mma_gemm1<<<dim3(NPTS / 128, NPTS / 128), 256>>>();
        ms_mma_gemm2<<<dim3(NPTS / 128, 2), 256>>>(cur, O);
        cur = O;
    }
}

// round 14
// speedup vs baseline: 4.2262x; 1.4727x over previous
#include <cuda_runtime.h>
#include <cuda_fp16.h>
#include <cstdint>

// Mean-shift clustering, 3 iterations, fp16 mma.sync m16n8k16 tensor cores.
// (tcgen05 unavailable: harness builds via compute_103 (non-'a').)
// fp16 has the same 10-bit significand as tf32 -> same accuracy, 2x the
// flops per HMMA instruction (the measured bottleneck: issue-rate-bound
// fallback HMMA at rt~25 cyc/SMSP).
//
//   S = X^T X ; K = exp(6 S) (symmetric) ; colsum[m] = row-sum of K
//   Out[d,m] = (sum_n K[m,n] X[d,n]) / colsum[m]
//
// g_K and g_XT are stored fp16: halves scratch traffic and removes cvt from
// the hot staging paths. GEMM1 computes only upper tile pairs (symmetry),
// writing each off-diagonal tile twice. colsum comes free from GEMM2's A
// prefetch registers (fp32 accumulation).
//
// NOTE: resubmission after a GB300 container-level failure (same signature
// as the R1/R2 infra flakes); kernel unchanged pending first measurement.

#define NPTS  8192
#define DFEAT 256
#define DELTA 6.0f
#define KC    32     // k floats per smem chunk = 2 x k16 mma slices
#define AST   20     // smem row stride in uint32 (16 half2 data + 4 pad)

__device__ __align__(16) __half g_K [(size_t)NPTS * NPTS];   // 128 MB
__device__ __align__(16) __half g_XT[(size_t)NPTS * DFEAT];  // 4 MB

__device__ __forceinline__ uint32_t f2h2(float a, float b) {
    __half2 h = __floats2half2_rn(a, b);
    return *reinterpret_cast<uint32_t*>(&h);
}
__device__ __forceinline__ float h2sum(uint32_t u) {
    float2 f = __half22float2(*reinterpret_cast<__half2*>(&u));
    return f.x + f.y;
}

__device__ __forceinline__ void mma16(float* c, const uint32_t* a, const uint32_t* b) {
    asm volatile(
        "mma.sync.aligned.m16n8k16.row.col.f32.f16.f16.f32 "
        "{%0,%1,%2,%3}, {%4,%5,%6,%7}, {%8,%9}, {%0,%1,%2,%3};"
        : "+f"(c[0]), "+f"(c[1]), "+f"(c[2]), "+f"(c[3])
        : "r"(a[0]), "r"(a[1]), "r"(a[2]), "r"(a[3]), "r"(b[0]), "r"(b[1]));
}

// ---------------------------------------------------------------------------
// Transpose + fp16 convert: g_XT[n][d] = fp16(X[d][n])
// ---------------------------------------------------------------------------
__global__ void __launch_bounds__(256) ms_transpose(const float* __restrict__ X) {
    __shared__ float t[32][33];
    const int tx = threadIdx.x, ty = threadIdx.y;
    const int n0 = blockIdx.x * 32, d0 = blockIdx.y * 32;
#pragma unroll
    for (int i = 0; i < 32; i += 8)
        t[ty + i][tx] = X[(size_t)(d0 + ty + i) * NPTS + n0 + tx];
    __syncthreads();
#pragma unroll
    for (int i = 0; i < 32; i += 8)
        g_XT[(size_t)(n0 + ty + i) * DFEAT + d0 + tx] = __float2half_rn(t[tx][ty + i]);
}

// ---------------------------------------------------------------------------
// GEMM1: g_K = fp16(exp(DELTA * X^T X)), symmetric -> upper tile pairs only.
// Block 128(n) x 128(m), k = 256 in 8 chunks of 32. 8 warps (2m x 4n),
// warp tile 64x32, mma m16n8k16.
// ---------------------------------------------------------------------------
__global__ void __launch_bounds__(256, 2) ms_mma_gemm1() {
    const int bx = blockIdx.x, by = blockIdx.y;
    if (bx < by) return;                 // lower-triangle tile pair: skip
    const bool diag = (bx == by);

    __shared__ uint32_t As[128 * AST];   // XT rows n0.. (half2 pairs)
    __shared__ uint32_t Bs[128 * AST];   // XT rows m0..

    const int tid  = threadIdx.x;
    const int n0   = by * 128, m0 = bx * 128;
    const int warp = tid >> 5, lane = tid & 31;
    const int g    = lane >> 2, t = lane & 3;
    const int wm   = (warp & 1) * 64;
    const int wn   = (warp >> 1) * 32;
    const int srow = tid >> 1;           // staging row 0..127
    const int sc   = (tid & 1) * 8;      // staging col base (uint32 units)

    float C[16][4];
#pragma unroll
    for (int i = 0; i < 16; ++i)
#pragma unroll
        for (int j = 0; j < 4; ++j) C[i][j] = 0.0f;

    // Row pointers in uint4 units (8 halves each); chunk = 4 uint4 per row.
    const uint4* gA = reinterpret_cast<const uint4*>(
        g_XT + (size_t)(n0 + srow) * DFEAT) + (tid & 1) * 2;
    const uint4* gB = reinterpret_cast<const uint4*>(
        g_XT + (size_t)(m0 + srow) * DFEAT) + (tid & 1) * 2;

    uint4 pa0 = gA[0], pa1 = gA[1];
    uint4 pb0 = gB[0], pb1 = gB[1];

#pragma unroll 1
    for (int c = 0; c < DFEAT / KC; ++c) {
        __syncthreads();
        *reinterpret_cast<uint4*>(As + srow * AST + sc)     = pa0;
        *reinterpret_cast<uint4*>(As + srow * AST + sc + 4) = pa1;
        *reinterpret_cast<uint4*>(Bs + srow * AST + sc)     = pb0;
        *reinterpret_cast<uint4*>(Bs + srow * AST + sc + 4) = pb1;
        __syncthreads();

        if (c + 1 < DFEAT / KC) {
            const int o = (c + 1) * 4;
            pa0 = gA[o]; pa1 = gA[o + 1];
            pb0 = gB[o]; pb1 = gB[o + 1];
        }

#pragma unroll
        for (int ks = 0; ks < 2; ++ks) {
            uint32_t bf[4][2];
#pragma unroll
            for (int nt = 0; nt < 4; ++nt) {
                const uint32_t* bp = Bs + (wn + nt * 8 + g) * AST + ks * 8 + t;
                bf[nt][0] = bp[0];
                bf[nt][1] = bp[4];
            }
#pragma unroll
            for (int mt = 0; mt < 4; ++mt) {
                const uint32_t* a0p = As + (wm + mt * 16 + g) * AST + ks * 8 + t;
                const uint32_t* a1p = a0p + 8 * AST;
                uint32_t af[4];
                af[0] = a0p[0];
                af[1] = a1p[0];
                af[2] = a0p[4];
                af[3] = a1p[4];
#pragma unroll
                for (int nt = 0; nt < 4; ++nt) mma16(C[mt * 4 + nt], af, bf[nt]);
            }
        }
    }

    // Epilogue. D[i][j] = S[n0+i][m0+j]; write exp() as fp16.
#pragma unroll
    for (int mt = 0; mt < 4; ++mt) {
#pragma unroll
        for (int nt = 0; nt < 4; ++nt) {
            const float* cc = C[mt * 4 + nt];
            const int i0 = wm + mt * 16 + g;
            const int j0 = wn + nt * 8 + 2 * t;
            const __half h0 = __float2half_rn(__expf(DELTA * cc[0]));
            const __half h1 = __float2half_rn(__expf(DELTA * cc[1]));
            const __half h2 = __float2half_rn(__expf(DELTA * cc[2]));
            const __half h3 = __float2half_rn(__expf(DELTA * cc[3]));

            // Transposed scatter: K[m0+j][n0+i] (covers row>=col half; full
            // tile when diagonal).
            g_K[(size_t)(m0 + j0)     * NPTS + n0 + i0]     = h0;
            g_K[(size_t)(m0 + j0 + 1) * NPTS + n0 + i0]     = h1;
            g_K[(size_t)(m0 + j0)     * NPTS + n0 + i0 + 8] = h2;
            g_K[(size_t)(m0 + j0 + 1) * NPTS + n0 + i0 + 8] = h3;

            if (!diag) {  // mirror: K[n0+i][m0+j], contiguous half2 stores
                *reinterpret_cast<__half2*>(g_K + (size_t)(n0 + i0)     * NPTS + m0 + j0) =
                    __halves2half2(h0, h1);
                *reinterpret_cast<__half2*>(g_K + (size_t)(n0 + i0 + 8) * NPTS + m0 + j0) =
                    __halves2half2(h2, h3);
            }
        }
    }
}

// ---------------------------------------------------------------------------
// GEMM2: Out[d,m] = (sum_n K[m,n] X[d,n]) / colsum[m]
// Block 128(m) x 128(d), k = 8192 in 256 chunks of 32; grid.y = 2.
// colsum accumulated in fp32 from the fp16 A prefetch registers.
// ---------------------------------------------------------------------------
__global__ void __launch_bounds__(256, 2) ms_mma_gemm2(const float* __restrict__ Xc,
                                                       float* __restrict__ Out) {
    __shared__ uint32_t As[128 * AST];   // K rows m0..
    __shared__ uint32_t Bs[128 * AST];   // X rows d0..
    __shared__ float cs_sm[128];

    const int tid  = threadIdx.x;
    const int m0   = blockIdx.x * 128, d0 = blockIdx.y * 128;
    const int warp = tid >> 5, lane = tid & 31;
    const int g    = lane >> 2, t = lane & 3;
    const int wm   = (warp & 1) * 64;
    const int wn   = (warp >> 1) * 32;
    const int srow = tid >> 1;
    const int sc   = (tid & 1) * 8;

    float C[16][4];
#pragma unroll
    for (int i = 0; i < 16; ++i)
#pragma unroll
        for (int j = 0; j < 4; ++j) C[i][j] = 0.0f;
    float csum = 0.0f;

    const uint4* gA = reinterpret_cast<const uint4*>(
        g_K + (size_t)(m0 + srow) * NPTS) + (tid & 1) * 2;
    const float* gB = Xc + (size_t)(d0 + srow) * NPTS + (tid & 1) * 16;

    uint4  pa0 = gA[0], pa1 = gA[1];
    float4 pb0 = *reinterpret_cast<const float4*>(gB);
    float4 pb1 = *reinterpret_cast<const float4*>(gB + 4);
    float4 pb2 = *reinterpret_cast<const float4*>(gB + 8);
    float4 pb3 = *reinterpret_cast<const float4*>(gB + 12);

#pragma unroll 1
    for (int c = 0; c < NPTS / KC; ++c) {
        __syncthreads();
        *reinterpret_cast<uint4*>(As + srow * AST + sc)     = pa0;
        *reinterpret_cast<uint4*>(As + srow * AST + sc + 4) = pa1;
        {
            uint32_t* bs = Bs + srow * AST + sc;
            bs[0] = f2h2(pb0.x, pb0.y); bs[1] = f2h2(pb0.z, pb0.w);
            bs[2] = f2h2(pb1.x, pb1.y); bs[3] = f2h2(pb1.z, pb1.w);
            bs[4] = f2h2(pb2.x, pb2.y); bs[5] = f2h2(pb2.z, pb2.w);
            bs[6] = f2h2(pb3.x, pb3.y); bs[7] = f2h2(pb3.z, pb3.w);
        }
        // colsum partial for row m0+srow (from this chunk's K values).
        csum += h2sum(pa0.x) + h2sum(pa0.y) + h2sum(pa0.z) + h2sum(pa0.w)
              + h2sum(pa1.x) + h2sum(pa1.y) + h2sum(pa1.z) + h2sum(pa1.w);
        __syncthreads();

        if (c + 1 < NPTS / KC) {
            const int o4 = (c + 1) * 4;         // uint4 units (A)
            const int of = (c + 1) * KC;        // float units (B)
            pa0 = gA[o4]; pa1 = gA[o4 + 1];
            pb0 = *reinterpret_cast<const float4*>(gB + of);
            pb1 = *reinterpret_cast<const float4*>(gB + of + 4);
            pb2 = *reinterpret_cast<const float4*>(gB + of + 8);
            pb3 = *reinterpret_cast<const float4*>(gB + of + 12);
        }

#pragma unroll
        for (int ks = 0; ks < 2; ++ks) {
            uint32_t bf[4][2];
#pragma unroll
            for (int nt = 0; nt < 4; ++nt) {
                const uint32_t* bp = Bs + (wn + nt * 8 + g) * AST + ks * 8 + t;
                bf[nt][0] = bp[0];
                bf[nt][1] = bp[4];
            }
#pragma unroll
            for (int mt = 0; mt < 4; ++mt) {
                const uint32_t* a0p = As + (wm + mt * 16 + g) * AST + ks * 8 + t;
                const uint32_t* a1p = a0p + 8 * AST;
                uint32_t af[4];
                af[0] = a0p[0];
                af[1] = a1p[0];
                af[2] = a0p[4];
                af[3] = a1p[4];
#pragma unroll
                for (int nt = 0; nt < 4; ++nt) mma16(C[mt * 4 + nt], af, bf[nt]);
            }
        }
    }

    // Finish colsum: threads (tid, tid^1) share row srow.
    csum += __shfl_xor_sync(0xffffffffu, csum, 1);
    if ((tid & 1) == 0) cs_sm[srow] = csum;
    __syncthreads();

    // Epilogue: Out[d0+j][m0+i] = D[i][j] / colsum[m0+i]
#pragma unroll
    for (int mt = 0; mt < 4; ++mt) {
        const int i0 = wm + mt * 16 + g;
        const float inv0 = 1.0f / cs_sm[i0];
        const float inv1 = 1.0f / cs_sm[i0 + 8];
#pragma unroll
        for (int nt = 0; nt < 4; ++nt) {
            const float* cc = C[mt * 4 + nt];
            const int j0 = wn + nt * 8 + 2 * t;
            float* r0 = Out + (size_t)(d0 + j0) * NPTS + m0 + i0;
            float* r1 = Out + (size_t)(d0 + j0 + 1) * NPTS + m0 + i0;
            r0[0] = cc[0] * inv0;
            r1[0] = cc[1] * inv0;
            r0[8] = cc[2] * inv1;
            r1[8] = cc[3] * inv1;
        }
    }
}

// ---------------------------------------------------------------------------
// Launch: 3 chained iterations; kernel launches only -> graph-capturable.
// ---------------------------------------------------------------------------
extern "C" void kernel_launch(void* const* d_in, const int* in_sizes, int n_in,
                              void* d_out, int out_size) {
    const float* X0 = (const float*)d_in[0];
    float* out = (float*)d_out;

    const float* cur = X0;
    for (int it = 0; it < 3; ++it) {
        float* O = out + (size_t)it * DFEAT * NPTS;
        ms_transpose<<<dim3(NPTS / 32, DFEAT / 32), dim3(32, 8)>>>(cur);
        ms_mma_gemm1<<<dim3(NPTS / 128, NPTS / 128), 256>>>();
        ms_mma_gemm2<<<dim3(NPTS / 128, 2), 256>>>(cur, O);
        cur = O;
    }
}

// round 15
// speedup vs baseline: 4.9323x; 1.1671x over previous
#include <cuda_runtime.h>
#include <cuda_fp16.h>
#include <cstdint>

// Mean-shift clustering, 3 iterations, fp16 mma.sync m16n8k16 tensor cores.
// (tcgen05 unavailable: harness builds via compute_103 (non-'a').)
//
//   S = X^T X ; K = exp(6 S) (symmetric) ; colsum[m] = row-sum of K
//   Out[d,m] = (sum_n K[m,n] X[d,n]) / colsum[m]
//
// GEMM1: 128x128 tiles, upper tile pairs only (symmetry), off-diagonal tiles
//        written twice (scatter + mirrored contiguous half2).
// GEMM2: retiled to 64(m) x 128(d) blocks -> 256 CTAs (was 128): fixes the
//        measured occupancy starvation (1 CTA/SM, 20 idle SMs) that made
//        GEMM2 2x slower per identical CTA-chunk than GEMM1.
// g_K, g_XT, g_Xh stored fp16 (same 10-bit significand as tf32; range safe:
// K <= e^5.4 ~ 222). colsum accumulated in fp32 from A prefetch registers.

#define NPTS  8192
#define DFEAT 256
#define DELTA 6.0f
#define KC    32     // k halves per smem chunk = 2 x k16 mma slices
#define AST   20     // smem row stride in uint32 (16 data + 4 pad)

__device__ __align__(16) __half g_K [(size_t)NPTS * NPTS];   // 128 MB
__device__ __align__(16) __half g_XT[(size_t)NPTS * DFEAT];  // 4 MB, [n][d]
__device__ __align__(16) __half g_Xh[(size_t)DFEAT * NPTS];  // 4 MB, [d][n]

__device__ __forceinline__ float h2sum(uint32_t u) {
    float2 f = __half22float2(*reinterpret_cast<__half2*>(&u));
    return f.x + f.y;
}

__device__ __forceinline__ void mma16(float* c, const uint32_t* a, const uint32_t* b) {
    asm volatile(
        "mma.sync.aligned.m16n8k16.row.col.f32.f16.f16.f32 "
        "{%0,%1,%2,%3}, {%4,%5,%6,%7}, {%8,%9}, {%0,%1,%2,%3};"
        : "+f"(c[0]), "+f"(c[1]), "+f"(c[2]), "+f"(c[3])
        : "r"(a[0]), "r"(a[1]), "r"(a[2]), "r"(a[3]), "r"(b[0]), "r"(b[1]));
}

// ---------------------------------------------------------------------------
// Transpose + fp16 convert: g_XT[n][d] = h(X[d][n]); g_Xh[d][n] = h(X[d][n]).
// ---------------------------------------------------------------------------
__global__ void __launch_bounds__(256) ms_transpose(const float* __restrict__ X) {
    __shared__ float t[32][33];
    const int tx = threadIdx.x, ty = threadIdx.y;
    const int n0 = blockIdx.x * 32, d0 = blockIdx.y * 32;
#pragma unroll
    for (int i = 0; i < 32; i += 8) {
        const float v = X[(size_t)(d0 + ty + i) * NPTS + n0 + tx];
        t[ty + i][tx] = v;
        g_Xh[(size_t)(d0 + ty + i) * NPTS + n0 + tx] = __float2half_rn(v);
    }
    __syncthreads();
#pragma unroll
    for (int i = 0; i < 32; i += 8)
        g_XT[(size_t)(n0 + ty + i) * DFEAT + d0 + tx] = __float2half_rn(t[tx][ty + i]);
}

// ---------------------------------------------------------------------------
// GEMM1: g_K = fp16(exp(DELTA * X^T X)), symmetric -> upper tile pairs only.
// Block 128(n) x 128(m), k = 256 in 8 chunks of 32. 8 warps (2m x 4n),
// warp tile 64x32, mma m16n8k16.
// ---------------------------------------------------------------------------
__global__ void __launch_bounds__(256, 2) ms_mma_gemm1() {
    const int bx = blockIdx.x, by = blockIdx.y;
    if (bx < by) return;                 // lower-triangle tile pair: skip
    const bool diag = (bx == by);

    __shared__ uint32_t As[128 * AST];   // XT rows n0.. (half2 pairs)
    __shared__ uint32_t Bs[128 * AST];   // XT rows m0..

    const int tid  = threadIdx.x;
    const int n0   = by * 128, m0 = bx * 128;
    const int warp = tid >> 5, lane = tid & 31;
    const int g    = lane >> 2, t = lane & 3;
    const int wm   = (warp & 1) * 64;
    const int wn   = (warp >> 1) * 32;
    const int srow = tid >> 1;           // staging row 0..127
    const int sc   = (tid & 1) * 8;      // staging col base (uint32 units)

    float C[16][4];
#pragma unroll
    for (int i = 0; i < 16; ++i)
#pragma unroll
        for (int j = 0; j < 4; ++j) C[i][j] = 0.0f;

    const uint4* gA = reinterpret_cast<const uint4*>(
        g_XT + (size_t)(n0 + srow) * DFEAT) + (tid & 1) * 2;
    const uint4* gB = reinterpret_cast<const uint4*>(
        g_XT + (size_t)(m0 + srow) * DFEAT) + (tid & 1) * 2;

    uint4 pa0 = gA[0], pa1 = gA[1];
    uint4 pb0 = gB[0], pb1 = gB[1];

#pragma unroll 1
    for (int c = 0; c < DFEAT / KC; ++c) {
        __syncthreads();
        *reinterpret_cast<uint4*>(As + srow * AST + sc)     = pa0;
        *reinterpret_cast<uint4*>(As + srow * AST + sc + 4) = pa1;
        *reinterpret_cast<uint4*>(Bs + srow * AST + sc)     = pb0;
        *reinterpret_cast<uint4*>(Bs + srow * AST + sc + 4) = pb1;
        __syncthreads();

        if (c + 1 < DFEAT / KC) {
            const int o = (c + 1) * 4;
            pa0 = gA[o]; pa1 = gA[o + 1];
            pb0 = gB[o]; pb1 = gB[o + 1];
        }

#pragma unroll
        for (int ks = 0; ks < 2; ++ks) {
            uint32_t bf[4][2];
#pragma unroll
            for (int nt = 0; nt < 4; ++nt) {
                const uint32_t* bp = Bs + (wn + nt * 8 + g) * AST + ks * 8 + t;
                bf[nt][0] = bp[0];
                bf[nt][1] = bp[4];
            }
#pragma unroll
            for (int mt = 0; mt < 4; ++mt) {
                const uint32_t* a0p = As + (wm + mt * 16 + g) * AST + ks * 8 + t;
                const uint32_t* a1p = a0p + 8 * AST;
                uint32_t af[4];
                af[0] = a0p[0];
                af[1] = a1p[0];
                af[2] = a0p[4];
                af[3] = a1p[4];
#pragma unroll
                for (int nt = 0; nt < 4; ++nt) mma16(C[mt * 4 + nt], af, bf[nt]);
            }
        }
    }

    // Epilogue. D[i][j] = S[n0+i][m0+j]; write exp() as fp16.
#pragma unroll
    for (int mt = 0; mt < 4; ++mt) {
#pragma unroll
        for (int nt = 0; nt < 4; ++nt) {
            const float* cc = C[mt * 4 + nt];
            const int i0 = wm + mt * 16 + g;
            const int j0 = wn + nt * 8 + 2 * t;
            const __half h0 = __float2half_rn(__expf(DELTA * cc[0]));
            const __half h1 = __float2half_rn(__expf(DELTA * cc[1]));
            const __half h2 = __float2half_rn(__expf(DELTA * cc[2]));
            const __half h3 = __float2half_rn(__expf(DELTA * cc[3]));

            g_K[(size_t)(m0 + j0)     * NPTS + n0 + i0]     = h0;
            g_K[(size_t)(m0 + j0 + 1) * NPTS + n0 + i0]     = h1;
            g_K[(size_t)(m0 + j0)     * NPTS + n0 + i0 + 8] = h2;
            g_K[(size_t)(m0 + j0 + 1) * NPTS + n0 + i0 + 8] = h3;

            if (!diag) {  // mirror: K[n0+i][m0+j], contiguous half2 stores
                *reinterpret_cast<__half2*>(g_K + (size_t)(n0 + i0)     * NPTS + m0 + j0) =
                    __halves2half2(h0, h1);
                *reinterpret_cast<__half2*>(g_K + (size_t)(n0 + i0 + 8) * NPTS + m0 + j0) =
                    __halves2half2(h2, h3);
            }
        }
    }
}

// ---------------------------------------------------------------------------
// GEMM2: Out[d,m] = (sum_n K[m,n] X[d,n]) / colsum[m]
// Block 64(m) x 128(d) -> grid (128, 2) = 256 CTAs (occupancy fix).
// 8 warps (2m x 4d), warp tile 32x32. k = 8192 in 256 chunks of 32.
// colsum accumulated in fp32 from the fp16 A prefetch registers.
// ---------------------------------------------------------------------------
__global__ void __launch_bounds__(256, 2) ms_mma_gemm2(float* __restrict__ Out) {
    __shared__ uint32_t As[64 * AST];    // K rows m0..m0+63
    __shared__ uint32_t Bs[128 * AST];   // Xh rows d0..d0+127
    __shared__ float cs_sm[64];

    const int tid  = threadIdx.x;
    const int m0   = blockIdx.x * 64, d0 = blockIdx.y * 128;
    const int warp = tid >> 5, lane = tid & 31;
    const int g    = lane >> 2, t = lane & 3;
    const int wm   = (warp & 1) * 32;
    const int wn   = (warp >> 1) * 32;
    const int arow = tid >> 2;           // A staging row 0..63 (4 thr/row)
    const int ac   = (tid & 3) * 4;      // A staging col (uint32 units)
    const int brow = tid >> 1;           // B staging row 0..127
    const int bc   = (tid & 1) * 8;      // B staging col (uint32 units)

    float C[8][4];
#pragma unroll
    for (int i = 0; i < 8; ++i)
#pragma unroll
        for (int j = 0; j < 4; ++j) C[i][j] = 0.0f;
    float csum = 0.0f;

    const uint4* gA = reinterpret_cast<const uint4*>(
        g_K + (size_t)(m0 + arow) * NPTS) + (tid & 3);
    const uint4* gB = reinterpret_cast<const uint4*>(
        g_Xh + (size_t)(d0 + brow) * NPTS) + (tid & 1) * 2;

    uint4 pa  = gA[0];
    uint4 pb0 = gB[0], pb1 = gB[1];

#pragma unroll 1
    for (int c = 0; c < NPTS / KC; ++c) {
        __syncthreads();
        *reinterpret_cast<uint4*>(As + arow * AST + ac)     = pa;
        *reinterpret_cast<uint4*>(Bs + brow * AST + bc)     = pb0;
        *reinterpret_cast<uint4*>(Bs + brow * AST + bc + 4) = pb1;
        // colsum partial for row m0+arow (this thread's 8 K halves).
        csum += h2sum(pa.x) + h2sum(pa.y) + h2sum(pa.z) + h2sum(pa.w);
        __syncthreads();

        if (c + 1 < NPTS / KC) {
            const int o = (c + 1) * 4;   // uint4 units per 32-half chunk
            pa  = gA[o];
            pb0 = gB[o]; pb1 = gB[o + 1];
        }

#pragma unroll
        for (int ks = 0; ks < 2; ++ks) {
            uint32_t bf[4][2];
#pragma unroll
            for (int nt = 0; nt < 4; ++nt) {
                const uint32_t* bp = Bs + (wn + nt * 8 + g) * AST + ks * 8 + t;
                bf[nt][0] = bp[0];
                bf[nt][1] = bp[4];
            }
#pragma unroll
            for (int mt = 0; mt < 2; ++mt) {
                const uint32_t* a0p = As + (wm + mt * 16 + g) * AST + ks * 8 + t;
                const uint32_t* a1p = a0p + 8 * AST;
                uint32_t af[4];
                af[0] = a0p[0];
                af[1] = a1p[0];
                af[2] = a0p[4];
                af[3] = a1p[4];
#pragma unroll
                for (int nt = 0; nt < 4; ++nt) mma16(C[mt * 4 + nt], af, bf[nt]);
            }
        }
    }

    // colsum: reduce the 4 loader threads (consecutive lanes) per row.
    csum += __shfl_xor_sync(0xffffffffu, csum, 1);
    csum += __shfl_xor_sync(0xffffffffu, csum, 2);
    if ((tid & 3) == 0) cs_sm[arow] = csum;
    __syncthreads();

    // Epilogue: Out[d0+j][m0+i] = D[i][j] / colsum[m0+i]
#pragma unroll
    for (int mt = 0; mt < 2; ++mt) {
        const int i0 = wm + mt * 16 + g;
        const float inv0 = 1.0f / cs_sm[i0];
        const float inv1 = 1.0f / cs_sm[i0 + 8];
#pragma unroll
        for (int nt = 0; nt < 4; ++nt) {
            const float* cc = C[mt * 4 + nt];
            const int j0 = wn + nt * 8 + 2 * t;
            float* r0 = Out + (size_t)(d0 + j0) * NPTS + m0 + i0;
            float* r1 = Out + (size_t)(d0 + j0 + 1) * NPTS + m0 + i0;
            r0[0] = cc[0] * inv0;
            r1[0] = cc[1] * inv0;
            r0[8] = cc[2] * inv1;
            r1[8] = cc[3] * inv1;
        }
    }
}

// ---------------------------------------------------------------------------
// Iteration chaining: iterations 2 and 3 need X_cur in fp32 for ms_transpose;
// Out (fp32) is in d_out, so transpose reads from there. Kernel launches only.
// ---------------------------------------------------------------------------
extern "C" void kernel_launch(void* const* d_in, const int* in_sizes, int n_in,
                              void* d_out, int out_size) {
    const float* X0 = (const float*)d_in[0];
    float* out = (float*)d_out;

    const float* cur = X0;
    for (int it = 0; it < 3; ++it) {
        float* O = out + (size_t)it * DFEAT * NPTS;
        ms_transpose<<<dim3(NPTS / 32, DFEAT / 32), dim3(32, 8)>>>(cur);
        ms_mma_gemm1<<<dim3(NPTS / 128, NPTS / 128), 256>>>();
        ms_mma_gemm2<<<dim3(NPTS / 64, 2), 256>>>(O);
        cur = O;
    }
}

// round 16
// speedup vs baseline: 5.4935x; 1.1138x over previous
#include <cuda_runtime.h>
#include <cuda_fp16.h>
#include <cstdint>

// Mean-shift clustering, 3 iterations, fp16 mma.sync m16n8k16 tensor cores.
// (tcgen05 unavailable: harness builds via compute_103 (non-'a').)
//
//   S = X^T X ; K = exp(6 S) (symmetric) ; colsum[m] = row-sum of K
//   Out[d,m] = (sum_n K[m,n] X[d,n]) / colsum[m]
//
// GEMM1: 128x128 tiles, upper tile pairs only (symmetry), off-diagonal tiles
//        written twice. Measured effective HMMA rt ~9.6 cyc -> untouched.
// GEMM2: 64(m) x 128(d) tiles, 256 CTAs (2/SM) AND KC=64 (32 mma/warp per
//        staging phase, half the syncs): combines the occupancy fix (R15)
//        with GEMM1's per-phase compute density (the measured missing 4x).
// g_K, g_XT, g_Xh stored fp16. colsum accumulated in fp32 from A prefetch.

#define NPTS  8192
#define DFEAT 256
#define DELTA 6.0f
#define KC    32     // GEMM1 chunk (k halves)
#define AST   20     // GEMM1 smem row stride in uint32 (16 data + 4 pad)
#define KC2   64     // GEMM2 chunk (k halves)
#define AST2  36     // GEMM2 smem row stride in uint32 (32 data + 4 pad)

__device__ __align__(16) __half g_K [(size_t)NPTS * NPTS];   // 128 MB
__device__ __align__(16) __half g_XT[(size_t)NPTS * DFEAT];  // 4 MB, [n][d]
__device__ __align__(16) __half g_Xh[(size_t)DFEAT * NPTS];  // 4 MB, [d][n]

__device__ __forceinline__ float h2sum(uint32_t u) {
    float2 f = __half22float2(*reinterpret_cast<__half2*>(&u));
    return f.x + f.y;
}

__device__ __forceinline__ void mma16(float* c, const uint32_t* a, const uint32_t* b) {
    asm volatile(
        "mma.sync.aligned.m16n8k16.row.col.f32.f16.f16.f32 "
        "{%0,%1,%2,%3}, {%4,%5,%6,%7}, {%8,%9}, {%0,%1,%2,%3};"
        : "+f"(c[0]), "+f"(c[1]), "+f"(c[2]), "+f"(c[3])
        : "r"(a[0]), "r"(a[1]), "r"(a[2]), "r"(a[3]), "r"(b[0]), "r"(b[1]));
}

// ---------------------------------------------------------------------------
// Transpose + fp16 convert: g_XT[n][d] = h(X[d][n]); g_Xh[d][n] = h(X[d][n]).
// ---------------------------------------------------------------------------
__global__ void __launch_bounds__(256) ms_transpose(const float* __restrict__ X) {
    __shared__ float t[32][33];
    const int tx = threadIdx.x, ty = threadIdx.y;
    const int n0 = blockIdx.x * 32, d0 = blockIdx.y * 32;
#pragma unroll
    for (int i = 0; i < 32; i += 8) {
        const float v = X[(size_t)(d0 + ty + i) * NPTS + n0 + tx];
        t[ty + i][tx] = v;
        g_Xh[(size_t)(d0 + ty + i) * NPTS + n0 + tx] = __float2half_rn(v);
    }
    __syncthreads();
#pragma unroll
    for (int i = 0; i < 32; i += 8)
        g_XT[(size_t)(n0 + ty + i) * DFEAT + d0 + tx] = __float2half_rn(t[tx][ty + i]);
}

// ---------------------------------------------------------------------------
// GEMM1: g_K = fp16(exp(DELTA * X^T X)), symmetric -> upper tile pairs only.
// Block 128(n) x 128(m), k = 256 in 8 chunks of 32. 8 warps (2m x 4n),
// warp tile 64x32, mma m16n8k16.  (UNCHANGED — measured rt ~9.6 cyc.)
// ---------------------------------------------------------------------------
__global__ void __launch_bounds__(256, 2) ms_mma_gemm1() {
    const int bx = blockIdx.x, by = blockIdx.y;
    if (bx < by) return;                 // lower-triangle tile pair: skip
    const bool diag = (bx == by);

    __shared__ uint32_t As[128 * AST];
    __shared__ uint32_t Bs[128 * AST];

    const int tid  = threadIdx.x;
    const int n0   = by * 128, m0 = bx * 128;
    const int warp = tid >> 5, lane = tid & 31;
    const int g    = lane >> 2, t = lane & 3;
    const int wm   = (warp & 1) * 64;
    const int wn   = (warp >> 1) * 32;
    const int srow = tid >> 1;
    const int sc   = (tid & 1) * 8;

    float C[16][4];
#pragma unroll
    for (int i = 0; i < 16; ++i)
#pragma unroll
        for (int j = 0; j < 4; ++j) C[i][j] = 0.0f;

    const uint4* gA = reinterpret_cast<const uint4*>(
        g_XT + (size_t)(n0 + srow) * DFEAT) + (tid & 1) * 2;
    const uint4* gB = reinterpret_cast<const uint4*>(
        g_XT + (size_t)(m0 + srow) * DFEAT) + (tid & 1) * 2;

    uint4 pa0 = gA[0], pa1 = gA[1];
    uint4 pb0 = gB[0], pb1 = gB[1];

#pragma unroll 1
    for (int c = 0; c < DFEAT / KC; ++c) {
        __syncthreads();
        *reinterpret_cast<uint4*>(As + srow * AST + sc)     = pa0;
        *reinterpret_cast<uint4*>(As + srow * AST + sc + 4) = pa1;
        *reinterpret_cast<uint4*>(Bs + srow * AST + sc)     = pb0;
        *reinterpret_cast<uint4*>(Bs + srow * AST + sc + 4) = pb1;
        __syncthreads();

        if (c + 1 < DFEAT / KC) {
            const int o = (c + 1) * 4;
            pa0 = gA[o]; pa1 = gA[o + 1];
            pb0 = gB[o]; pb1 = gB[o + 1];
        }

#pragma unroll
        for (int ks = 0; ks < 2; ++ks) {
            uint32_t bf[4][2];
#pragma unroll
            for (int nt = 0; nt < 4; ++nt) {
                const uint32_t* bp = Bs + (wn + nt * 8 + g) * AST + ks * 8 + t;
                bf[nt][0] = bp[0];
                bf[nt][1] = bp[4];
            }
#pragma unroll
            for (int mt = 0; mt < 4; ++mt) {
                const uint32_t* a0p = As + (wm + mt * 16 + g) * AST + ks * 8 + t;
                const uint32_t* a1p = a0p + 8 * AST;
                uint32_t af[4];
                af[0] = a0p[0];
                af[1] = a1p[0];
                af[2] = a0p[4];
                af[3] = a1p[4];
#pragma unroll
                for (int nt = 0; nt < 4; ++nt) mma16(C[mt * 4 + nt], af, bf[nt]);
            }
        }
    }

    // Epilogue. D[i][j] = S[n0+i][m0+j]; write exp() as fp16.
#pragma unroll
    for (int mt = 0; mt < 4; ++mt) {
#pragma unroll
        for (int nt = 0; nt < 4; ++nt) {
            const float* cc = C[mt * 4 + nt];
            const int i0 = wm + mt * 16 + g;
            const int j0 = wn + nt * 8 + 2 * t;
            const __half h0 = __float2half_rn(__expf(DELTA * cc[0]));
            const __half h1 = __float2half_rn(__expf(DELTA * cc[1]));
            const __half h2 = __float2half_rn(__expf(DELTA * cc[2]));
            const __half h3 = __float2half_rn(__expf(DELTA * cc[3]));

            g_K[(size_t)(m0 + j0)     * NPTS + n0 + i0]     = h0;
            g_K[(size_t)(m0 + j0 + 1) * NPTS + n0 + i0]     = h1;
            g_K[(size_t)(m0 + j0)     * NPTS + n0 + i0 + 8] = h2;
            g_K[(size_t)(m0 + j0 + 1) * NPTS + n0 + i0 + 8] = h3;

            if (!diag) {
                *reinterpret_cast<__half2*>(g_K + (size_t)(n0 + i0)     * NPTS + m0 + j0) =
                    __halves2half2(h0, h1);
                *reinterpret_cast<__half2*>(g_K + (size_t)(n0 + i0 + 8) * NPTS + m0 + j0) =
                    __halves2half2(h2, h3);
            }
        }
    }
}

// ---------------------------------------------------------------------------
// GEMM2: Out[d,m] = (sum_n K[m,n] X[d,n]) / colsum[m]
// Block 64(m) x 128(d), grid (128, 2) = 256 CTAs, 2/SM. KC2 = 64:
// 32 mma/warp per staging phase, 128 phases. 8 warps (2m x 4d),
// warp tile 32x32. colsum in fp32 from the A prefetch registers.
// ---------------------------------------------------------------------------
__global__ void __launch_bounds__(256, 2) ms_mma_gemm2(float* __restrict__ Out) {
    __shared__ uint32_t As[64 * AST2];    // K rows m0..m0+63, 64 halves/chunk
    __shared__ uint32_t Bs[128 * AST2];   // Xh rows d0..d0+127
    __shared__ float cs_sm[64];

    const int tid  = threadIdx.x;
    const int m0   = blockIdx.x * 64, d0 = blockIdx.y * 128;
    const int warp = tid >> 5, lane = tid & 31;
    const int g    = lane >> 2, t = lane & 3;
    const int wm   = (warp & 1) * 32;
    const int wn   = (warp >> 1) * 32;
    const int arow = tid >> 2;            // A staging row 0..63 (4 thr/row)
    const int ac   = (tid & 3) * 8;       // A staging col (uint32 units)
    const int brow = tid >> 1;            // B staging row 0..127
    const int bc   = (tid & 1) * 16;      // B staging col (uint32 units)

    float C[8][4];
#pragma unroll
    for (int i = 0; i < 8; ++i)
#pragma unroll
        for (int j = 0; j < 4; ++j) C[i][j] = 0.0f;
    float csum = 0.0f;

    // Per chunk (64 halves = 8 uint4 per row): A thread loads 2 uint4,
    // B thread loads 4 uint4.
    const uint4* gA = reinterpret_cast<const uint4*>(
        g_K + (size_t)(m0 + arow) * NPTS) + (tid & 3) * 2;
    const uint4* gB = reinterpret_cast<const uint4*>(
        g_Xh + (size_t)(d0 + brow) * NPTS) + (tid & 1) * 4;

    uint4 pa0 = gA[0], pa1 = gA[1];
    uint4 pb0 = gB[0], pb1 = gB[1], pb2 = gB[2], pb3 = gB[3];

#pragma unroll 1
    for (int c = 0; c < NPTS / KC2; ++c) {
        __syncthreads();
        *reinterpret_cast<uint4*>(As + arow * AST2 + ac)      = pa0;
        *reinterpret_cast<uint4*>(As + arow * AST2 + ac + 4)  = pa1;
        *reinterpret_cast<uint4*>(Bs + brow * AST2 + bc)      = pb0;
        *reinterpret_cast<uint4*>(Bs + brow * AST2 + bc + 4)  = pb1;
        *reinterpret_cast<uint4*>(Bs + brow * AST2 + bc + 8)  = pb2;
        *reinterpret_cast<uint4*>(Bs + brow * AST2 + bc + 12) = pb3;
        // colsum partial for row m0+arow (this thread's 16 K halves).
        csum += h2sum(pa0.x) + h2sum(pa0.y) + h2sum(pa0.z) + h2sum(pa0.w)
              + h2sum(pa1.x) + h2sum(pa1.y) + h2sum(pa1.z) + h2sum(pa1.w);
        __syncthreads();

        if (c + 1 < NPTS / KC2) {
            const int o = (c + 1) * 8;    // uint4 per row per 64-half chunk
            pa0 = gA[o];     pa1 = gA[o + 1];
            pb0 = gB[o];     pb1 = gB[o + 1];
            pb2 = gB[o + 2]; pb3 = gB[o + 3];
        }

#pragma unroll
        for (int ks = 0; ks < 4; ++ks) {
            uint32_t bf[4][2];
#pragma unroll
            for (int nt = 0; nt < 4; ++nt) {
                const uint32_t* bp = Bs + (wn + nt * 8 + g) * AST2 + ks * 8 + t;
                bf[nt][0] = bp[0];
                bf[nt][1] = bp[4];
            }
#pragma unroll
            for (int mt = 0; mt < 2; ++mt) {
                const uint32_t* a0p = As + (wm + mt * 16 + g) * AST2 + ks * 8 + t;
                const uint32_t* a1p = a0p + 8 * AST2;
                uint32_t af[4];
                af[0] = a0p[0];
                af[1] = a1p[0];
                af[2] = a0p[4];
                af[3] = a1p[4];
#pragma unroll
                for (int nt = 0; nt < 4; ++nt) mma16(C[mt * 4 + nt], af, bf[nt]);
            }
        }
    }

    // colsum: reduce the 4 loader threads (consecutive lanes) per row.
    csum += __shfl_xor_sync(0xffffffffu, csum, 1);
    csum += __shfl_xor_sync(0xffffffffu, csum, 2);
    if ((tid & 3) == 0) cs_sm[arow] = csum;
    __syncthreads();

    // Epilogue: Out[d0+j][m0+i] = D[i][j] / colsum[m0+i]
#pragma unroll
    for (int mt = 0; mt < 2; ++mt) {
        const int i0 = wm + mt * 16 + g;
        const float inv0 = 1.0f / cs_sm[i0];
        const float inv1 = 1.0f / cs_sm[i0 + 8];
#pragma unroll
        for (int nt = 0; nt < 4; ++nt) {
            const float* cc = C[mt * 4 + nt];
            const int j0 = wn + nt * 8 + 2 * t;
            float* r0 = Out + (size_t)(d0 + j0) * NPTS + m0 + i0;
            float* r1 = Out + (size_t)(d0 + j0 + 1) * NPTS + m0 + i0;
            r0[0] = cc[0] * inv0;
            r1[0] = cc[1] * inv0;
            r0[8] = cc[2] * inv1;
            r1[8] = cc[3] * inv1;
        }
    }
}

// ---------------------------------------------------------------------------
// Launch: 3 chained iterations; kernel launches only -> graph-capturable.
// ---------------------------------------------------------------------------
extern "C" void kernel_launch(void* const* d_in, const int* in_sizes, int n_in,
                              void* d_out, int out_size) {
    const float* X0 = (const float*)d_in[0];
    float* out = (float*)d_out;

    const float* cur = X0;
    for (int it = 0; it < 3; ++it) {
        float* O = out + (size_t)it * DFEAT * NPTS;
        ms_transpose<<<dim3(NPTS / 32, DFEAT / 32), dim3(32, 8)>>>(cur);
        ms_mma_gemm1<<<dim3(NPTS / 128, NPTS / 128), 256>>>();
        ms_mma_gemm2<<<dim3(NPTS / 64, 2), 256>>>(O);
        cur = O;
    }
}